// round 14
// baseline (speedup 1.0000x reference)
#include <cuda_runtime.h>
#include <cuda_bf16.h>
#include <cstdint>

#define NU 200000
#define NI 100000
#define NE 1000000
#define HD 64
#define OD 32
#define CHUNK 1024   // elements per scan chunk (256 threads * 4)

// ---------------- device scratch (static globals: allocation-guard safe) ----------------
__device__ float g_hu[(size_t)NU * HD];
__device__ float g_hi[(size_t)NI * HD];
__device__ float g_x1u[(size_t)NU * HD];
__device__ float g_x1i[(size_t)NI * HD];
__device__ int   g_csr_u2i[NE];
__device__ int   g_csr_i2u[NE];
__device__ int   g_rsu[NU + 1];
__device__ int   g_rsi[NI + 1];
__device__ int   g_curu[NU];
__device__ int   g_curi[NI];
__device__ int   g_partU[256];
__device__ int   g_partI[256];

// ---------------- zero both cursor arrays ----------------
__global__ void zero_both_kernel(int* __restrict__ curu, int* __restrict__ curi) {
    int i = blockIdx.x * blockDim.x + threadIdx.x;
    if (i < NU) curu[i] = 0;
    else if (i < NU + NI) curi[i - NU] = 0;
}

// ---------------- histogram both edge types ----------------
__global__ void hist_both_kernel(const int* __restrict__ ei_u2i, const int* __restrict__ ei_i2u,
                                 int* __restrict__ curi, int* __restrict__ curu, int eb) {
    int b = blockIdx.x;
    if (b < eb) {
        int e = b * 256 + threadIdx.x;
        if (e < NE) atomicAdd(&curi[__ldg(ei_u2i + NE + e)], 1);
    } else {
        int e = (b - eb) * 256 + threadIdx.x;
        if (e < NE) atomicAdd(&curu[__ldg(ei_i2u + NE + e)], 1);
    }
}

// ---------------- chunked scan phase 1: per-chunk sums (both types) ----------------
__global__ void chunk_both_kernel(const int* __restrict__ degI, int* __restrict__ partI, int nbi,
                                  const int* __restrict__ degU, int* __restrict__ partU) {
    __shared__ int sc[256];
    int tid = threadIdx.x;
    const int* deg; int* part; int n, b;
    if (blockIdx.x < nbi) { deg = degI; part = partI; n = NI; b = blockIdx.x; }
    else { deg = degU; part = partU; n = NU; b = blockIdx.x - nbi; }
    int base = b * CHUNK + tid * 4;
    int s = 0;
    #pragma unroll
    for (int j = 0; j < 4; j++) { int idx = base + j; if (idx < n) s += deg[idx]; }
    sc[tid] = s; __syncthreads();
    for (int d = 128; d; d >>= 1) { if (tid < d) sc[tid] += sc[tid + d]; __syncthreads(); }
    if (tid == 0) part[b] = sc[0];
}

// ---------------- chunked scan phase 2: scan partials for both (one block) ----------------
__device__ void scan_part_one(int* __restrict__ part, int nblk) {
    __shared__ int sc[256];
    int tid = threadIdx.x;
    int v = (tid < nblk) ? part[tid] : 0;
    sc[tid] = v; __syncthreads();
    for (int d = 1; d < 256; d <<= 1) {
        int t = (tid >= d) ? sc[tid - d] : 0;
        __syncthreads();
        sc[tid] += t;
        __syncthreads();
    }
    if (tid < nblk) part[tid] = sc[tid] - v;   // exclusive
    __syncthreads();
}

__global__ void scan_parts_kernel(int* __restrict__ partI, int nbi,
                                  int* __restrict__ partU, int nbu) {
    scan_part_one(partI, nbi);
    scan_part_one(partU, nbu);
}

// ---------------- chunked scan phase 3: write exclusive scan (both types) ----------------
__global__ void scanwrite_both_kernel(int* __restrict__ curi, const int* __restrict__ partI,
                                      int* __restrict__ rsi, int nbi,
                                      int* __restrict__ curu, const int* __restrict__ partU,
                                      int* __restrict__ rsu) {
    __shared__ int sc[256];
    int tid = threadIdx.x;
    int* deg; const int* part; int* rs; int n, b;
    if (blockIdx.x < nbi) { deg = curi; part = partI; rs = rsi; n = NI; b = blockIdx.x; }
    else { deg = curu; part = partU; rs = rsu; n = NU; b = blockIdx.x - nbi; }
    int base = b * CHUNK + tid * 4;
    int v[4]; int s = 0;
    #pragma unroll
    for (int j = 0; j < 4; j++) { int idx = base + j; v[j] = (idx < n) ? deg[idx] : 0; s += v[j]; }
    sc[tid] = s; __syncthreads();
    for (int d = 1; d < 256; d <<= 1) {
        int t = (tid >= d) ? sc[tid - d] : 0;
        __syncthreads();
        sc[tid] += t;
        __syncthreads();
    }
    int off = part[b] + (sc[tid] - s);
    #pragma unroll
    for (int j = 0; j < 4; j++) {
        int idx = base + j;
        if (idx < n) { rs[idx] = off; deg[idx] = off; }   // deg becomes fill cursor
        off += v[j];
    }
    if (b == 0 && tid == 0) rs[n] = NE;
}

// ---------------- fill both CSR arrays ----------------
__global__ void fill_both_kernel(const int* __restrict__ ei_u2i, const int* __restrict__ ei_i2u,
                                 int* __restrict__ curi, int* __restrict__ curu,
                                 int* __restrict__ csr_u2i, int* __restrict__ csr_i2u, int eb) {
    int b = blockIdx.x;
    if (b < eb) {
        int e = b * 256 + threadIdx.x;
        if (e < NE) {
            int pos = atomicAdd(&curi[__ldg(ei_u2i + NE + e)], 1);
            csr_u2i[pos] = __ldg(ei_u2i + e);
        }
    } else {
        int e = (b - eb) * 256 + threadIdx.x;
        if (e < NE) {
            int pos = atomicAdd(&curu[__ldg(ei_i2u + NE + e)], 1);
            csr_i2u[pos] = __ldg(ei_i2u + e);
        }
    }
}

// ---------------- fused linear pair: out[n,COLS] = x[n,64] @ W[COLS,64]^T + b ----------------
template <int COLS>
__global__ void __launch_bounds__(256) linear_pair_kernel(
    const float* __restrict__ x0, const float* __restrict__ W0,
    const float* __restrict__ b0, float* __restrict__ out0, int n0, int nb0,
    const float* __restrict__ x1, const float* __restrict__ W1,
    const float* __restrict__ b1, float* __restrict__ out1, int n1)
{
    const float *x, *W, *bias; float* out; int n, row0;
    if (blockIdx.x < nb0) { x = x0; W = W0; bias = b0; out = out0; n = n0; row0 = blockIdx.x * 64; }
    else { x = x1; W = W1; bias = b1; out = out1; n = n1; row0 = (blockIdx.x - nb0) * 64; }

    constexpr int WS = COLS + 4;
    __shared__ float sW[64 * WS];
    __shared__ float sX[64 * 68];
    int tid = threadIdx.x;

    for (int i = tid; i < COLS * 64; i += 256) {
        int c = i >> 6, k = i & 63;
        sW[k * WS + c] = W[i];
    }
    for (int i = tid; i < 64 * 16; i += 256) {
        int r = i >> 4, q = i & 15;
        int row = row0 + r;
        float4 v = make_float4(0.f, 0.f, 0.f, 0.f);
        if (row < n) v = __ldg((const float4*)(x + (size_t)row * 64) + q);
        *(float4*)&sX[r * 68 + q * 4] = v;
    }
    __syncthreads();

    constexpr int CPT = COLS / 4;
    int r = tid >> 2, sub = tid & 3;
    int c0 = sub * CPT;
    float o[CPT];
    #pragma unroll
    for (int i = 0; i < CPT; i++) o[i] = __ldg(bias + c0 + i);

    #pragma unroll 4
    for (int k = 0; k < 64; k++) {
        float xv = sX[r * 68 + k];
        #pragma unroll
        for (int i = 0; i < CPT / 4; i++) {
            float4 w = *(const float4*)&sW[k * WS + c0 + 4 * i];
            o[4 * i + 0] += xv * w.x;
            o[4 * i + 1] += xv * w.y;
            o[4 * i + 2] += xv * w.z;
            o[4 * i + 3] += xv * w.w;
        }
    }
    int row = row0 + r;
    if (row < n) {
        #pragma unroll
        for (int i = 0; i < CPT / 4; i++) {
            float4 v = make_float4(o[4 * i], o[4 * i + 1], o[4 * i + 2], o[4 * i + 3]);
            ((float4*)(out + (size_t)row * COLS + c0))[i] = v;
        }
    }
}

// ---- single-side fused conv pass (SEPARATE launch per side: preserves L2 residency) ----
// 256 threads, 64 rows/block. Gather: 4 threads/row, 2-edge unrolled, no shuffles.
// GEMM: 2 rows x 8 cols register tiles (2.67 FMA/LDS-byte). ~32 warps/SM.
__global__ void __launch_bounds__(256) combine_kernel(
    const float* __restrict__ feat, const float* __restrict__ h,
    const int* __restrict__ rs, const int* __restrict__ csr,
    const float* __restrict__ Wrel, const float* __restrict__ brel,
    const float* __restrict__ Wroot,
    float* __restrict__ out, int n)
{
    __shared__ float sW[64 * 68];   // 17408 B
    __shared__ float sA[64 * 68];   // 17408 B
    int tid = threadIdx.x;
    int row0 = blockIdx.x * 64;

    // load Wrel: W row-major [c][k] -> sW[k*68+c]  (issued before gather; no sync yet)
    for (int i = tid; i < 4096; i += 256) {
        int c = i >> 6, k = i & 63;
        sW[k * 68 + c] = __ldg(Wrel + i);
    }

    // ---- gather mean: 4 threads/row, each owns 16 floats; 2-edge unroll ----
    {
        int r = tid >> 2, q = tid & 3;      // row 0..63, quarter 0..3
        int row = row0 + r;
        bool valid = row < n;
        int e0 = valid ? __ldg(rs + row) : 0;
        int e1 = valid ? __ldg(rs + row + 1) : 0;
        float acc[16];
        #pragma unroll
        for (int i = 0; i < 16; i++) acc[i] = 0.f;

        int e = e0;
        for (; e + 2 <= e1; e += 2) {
            int s0 = __ldg(csr + e);
            int s1 = __ldg(csr + e + 1);
            const float4* p0 = (const float4*)(feat + (size_t)s0 * 64) + q * 4;
            const float4* p1 = (const float4*)(feat + (size_t)s1 * 64) + q * 4;
            float4 a0 = __ldg(p0),     a1 = __ldg(p0 + 1);
            float4 a2 = __ldg(p0 + 2), a3 = __ldg(p0 + 3);
            float4 b0 = __ldg(p1),     b1 = __ldg(p1 + 1);
            float4 b2 = __ldg(p1 + 2), b3 = __ldg(p1 + 3);
            acc[0]  += a0.x + b0.x;  acc[1]  += a0.y + b0.y;
            acc[2]  += a0.z + b0.z;  acc[3]  += a0.w + b0.w;
            acc[4]  += a1.x + b1.x;  acc[5]  += a1.y + b1.y;
            acc[6]  += a1.z + b1.z;  acc[7]  += a1.w + b1.w;
            acc[8]  += a2.x + b2.x;  acc[9]  += a2.y + b2.y;
            acc[10] += a2.z + b2.z;  acc[11] += a2.w + b2.w;
            acc[12] += a3.x + b3.x;  acc[13] += a3.y + b3.y;
            acc[14] += a3.z + b3.z;  acc[15] += a3.w + b3.w;
        }
        if (e < e1) {
            int s0 = __ldg(csr + e);
            const float4* p0 = (const float4*)(feat + (size_t)s0 * 64) + q * 4;
            float4 a0 = __ldg(p0),     a1 = __ldg(p0 + 1);
            float4 a2 = __ldg(p0 + 2), a3 = __ldg(p0 + 3);
            acc[0]  += a0.x;  acc[1]  += a0.y;  acc[2]  += a0.z;  acc[3]  += a0.w;
            acc[4]  += a1.x;  acc[5]  += a1.y;  acc[6]  += a1.z;  acc[7]  += a1.w;
            acc[8]  += a2.x;  acc[9]  += a2.y;  acc[10] += a2.z;  acc[11] += a2.w;
            acc[12] += a3.x;  acc[13] += a3.y;  acc[14] += a3.z;  acc[15] += a3.w;
        }
        float id = 1.f / fmaxf((float)(e1 - e0), 1.f);
        float* dst = &sA[r * 68 + q * 16];
        #pragma unroll
        for (int j = 0; j < 4; j++) {
            *(float4*)(dst + 4 * j) = make_float4(acc[4 * j] * id, acc[4 * j + 1] * id,
                                                  acc[4 * j + 2] * id, acc[4 * j + 3] * id);
        }
    }
    __syncthreads();

    // register tile: 2 rows x 8 cols
    int rg = tid >> 3, cg = tid & 7;
    int r0t = rg * 2, c0 = cg * 8;
    float o[16];
    {
        float4 b0 = __ldg((const float4*)(brel + c0));
        float4 b1 = __ldg((const float4*)(brel + c0) + 1);
        #pragma unroll
        for (int i = 0; i < 2; i++) {
            o[8 * i + 0] = b0.x;  o[8 * i + 1] = b0.y;
            o[8 * i + 2] = b0.z;  o[8 * i + 3] = b0.w;
            o[8 * i + 4] = b1.x;  o[8 * i + 5] = b1.y;
            o[8 * i + 6] = b1.z;  o[8 * i + 7] = b1.w;
        }
    }

    // GEMM1: o += mean @ Wrel^T
    #pragma unroll 4
    for (int k = 0; k < 64; k++) {
        float4 w0 = *(const float4*)&sW[k * 68 + c0];
        float4 w1 = *(const float4*)&sW[k * 68 + c0 + 4];
        #pragma unroll
        for (int i = 0; i < 2; i++) {
            float a = sA[(r0t + i) * 68 + k];
            o[8 * i + 0] += a * w0.x;  o[8 * i + 1] += a * w0.y;
            o[8 * i + 2] += a * w0.z;  o[8 * i + 3] += a * w0.w;
            o[8 * i + 4] += a * w1.x;  o[8 * i + 5] += a * w1.y;
            o[8 * i + 6] += a * w1.z;  o[8 * i + 7] += a * w1.w;
        }
    }
    __syncthreads();

    // reload: sW <- Wroot, sA <- h
    for (int i = tid; i < 4096; i += 256) {
        int c = i >> 6, k = i & 63;
        sW[k * 68 + c] = __ldg(Wroot + i);
    }
    for (int i = tid; i < 1024; i += 256) {
        int r = i >> 4, q = i & 15;
        int row = row0 + r;
        float4 v = make_float4(0.f, 0.f, 0.f, 0.f);
        if (row < n) v = __ldg((const float4*)(h + (size_t)row * 64) + q);
        *(float4*)&sA[r * 68 + q * 4] = v;
    }
    __syncthreads();

    // GEMM2: o += h @ Wroot^T
    #pragma unroll 4
    for (int k = 0; k < 64; k++) {
        float4 w0 = *(const float4*)&sW[k * 68 + c0];
        float4 w1 = *(const float4*)&sW[k * 68 + c0 + 4];
        #pragma unroll
        for (int i = 0; i < 2; i++) {
            float a = sA[(r0t + i) * 68 + k];
            o[8 * i + 0] += a * w0.x;  o[8 * i + 1] += a * w0.y;
            o[8 * i + 2] += a * w0.z;  o[8 * i + 3] += a * w0.w;
            o[8 * i + 4] += a * w1.x;  o[8 * i + 5] += a * w1.y;
            o[8 * i + 6] += a * w1.z;  o[8 * i + 7] += a * w1.w;
        }
    }

    // epilogue: + skip(h) -> relu -> store
    #pragma unroll
    for (int i = 0; i < 2; i++) {
        int row = row0 + r0t + i;
        if (row < n) {
            float4 s0 = *(const float4*)&sA[(r0t + i) * 68 + c0];
            float4 s1 = *(const float4*)&sA[(r0t + i) * 68 + c0 + 4];
            float4 v0, v1;
            v0.x = fmaxf(o[8 * i + 0] + s0.x, 0.f);
            v0.y = fmaxf(o[8 * i + 1] + s0.y, 0.f);
            v0.z = fmaxf(o[8 * i + 2] + s0.z, 0.f);
            v0.w = fmaxf(o[8 * i + 3] + s0.w, 0.f);
            v1.x = fmaxf(o[8 * i + 4] + s1.x, 0.f);
            v1.y = fmaxf(o[8 * i + 5] + s1.y, 0.f);
            v1.z = fmaxf(o[8 * i + 6] + s1.z, 0.f);
            v1.w = fmaxf(o[8 * i + 7] + s1.w, 0.f);
            float4* op = (float4*)(out + (size_t)row * 64 + c0);
            op[0] = v0;
            op[1] = v1;
        }
    }
}

// ---------------- host ----------------
extern "C" void kernel_launch(void* const* d_in, const int* in_sizes, int n_in,
                              void* d_out, int out_size)
{
    const float* x_user = (const float*)d_in[0];
    const float* x_item = (const float*)d_in[1];
    const int*   ei_u2i = (const int*)d_in[2];
    const int*   ei_i2u = (const int*)d_in[3];
    const float* pre_w_u = (const float*)d_in[4];
    const float* pre_b_u = (const float*)d_in[5];
    const float* pre_w_i = (const float*)d_in[6];
    const float* pre_b_i = (const float*)d_in[7];
    const float* c1u2i_wrel  = (const float*)d_in[8];
    const float* c1u2i_brel  = (const float*)d_in[9];
    const float* c1u2i_wroot = (const float*)d_in[10];
    const float* c1i2u_wrel  = (const float*)d_in[11];
    const float* c1i2u_brel  = (const float*)d_in[12];
    const float* c1i2u_wroot = (const float*)d_in[13];
    const float* c2u2i_wrel  = (const float*)d_in[14];
    const float* c2u2i_brel  = (const float*)d_in[15];
    const float* c2u2i_wroot = (const float*)d_in[16];
    const float* c2i2u_wrel  = (const float*)d_in[17];
    const float* c2i2u_brel  = (const float*)d_in[18];
    const float* c2i2u_wroot = (const float*)d_in[19];
    const float* post_w_u = (const float*)d_in[20];
    const float* post_b_u = (const float*)d_in[21];
    const float* post_w_i = (const float*)d_in[22];
    const float* post_b_i = (const float*)d_in[23];
    float* out_u = (float*)d_out;
    float* out_i = out_u + (size_t)NU * OD;

    float *hu, *hi, *x1u, *x1i;
    int *csr_u2i, *csr_i2u, *rsu, *rsi, *curu, *curi, *partU, *partI;
    cudaGetSymbolAddress((void**)&hu,  g_hu);
    cudaGetSymbolAddress((void**)&hi,  g_hi);
    cudaGetSymbolAddress((void**)&x1u, g_x1u);
    cudaGetSymbolAddress((void**)&x1i, g_x1i);
    cudaGetSymbolAddress((void**)&csr_u2i, g_csr_u2i);
    cudaGetSymbolAddress((void**)&csr_i2u, g_csr_i2u);
    cudaGetSymbolAddress((void**)&rsu,  g_rsu);
    cudaGetSymbolAddress((void**)&rsi,  g_rsi);
    cudaGetSymbolAddress((void**)&curu, g_curu);
    cudaGetSymbolAddress((void**)&curi, g_curi);
    cudaGetSymbolAddress((void**)&partU, g_partU);
    cudaGetSymbolAddress((void**)&partI, g_partI);

    const int EB = (NE + 255) / 256;
    const int NUB64 = (NU + 63) / 64, NIB64 = (NI + 63) / 64;
    const int NBLKI = (NI + CHUNK - 1) / CHUNK;   // 98
    const int NBLKU = (NU + CHUNK - 1) / CHUNK;   // 196

    // CSR build
    zero_both_kernel<<<(NU + NI + 255) / 256, 256>>>(curu, curi);
    hist_both_kernel<<<2 * EB, 256>>>(ei_u2i, ei_i2u, curi, curu, EB);
    chunk_both_kernel<<<NBLKI + NBLKU, 256>>>(curi, partI, NBLKI, curu, partU);
    scan_parts_kernel<<<1, 256>>>(partI, NBLKI, partU, NBLKU);
    scanwrite_both_kernel<<<NBLKI + NBLKU, 256>>>(curi, partI, rsi, NBLKI, curu, partU, rsu);
    fill_both_kernel<<<2 * EB, 256>>>(ei_u2i, ei_i2u, curi, curu, csr_u2i, csr_i2u, EB);

    // preprocess linears
    linear_pair_kernel<64><<<NUB64 + NIB64, 256>>>(x_user, pre_w_u, pre_b_u, hu, NU, NUB64,
                                                   x_item, pre_w_i, pre_b_i, hi, NI);
    // layer 1 (separate launches: each pass keeps its feature table L2-resident)
    combine_kernel<<<NIB64, 256>>>(hu, hi, rsi, csr_u2i,
                                   c1u2i_wrel, c1u2i_brel, c1u2i_wroot, x1i, NI);
    combine_kernel<<<NUB64, 256>>>(hi, hu, rsu, csr_i2u,
                                   c1i2u_wrel, c1i2u_brel, c1i2u_wroot, x1u, NU);
    // layer 2 (outputs overwrite pre-linear buffers)
    combine_kernel<<<NIB64, 256>>>(x1u, x1i, rsi, csr_u2i,
                                   c2u2i_wrel, c2u2i_brel, c2u2i_wroot, hi, NI);
    combine_kernel<<<NUB64, 256>>>(x1i, x1u, rsu, csr_i2u,
                                   c2i2u_wrel, c2i2u_brel, c2i2u_wroot, hu, NU);
    // postprocess linears -> output
    linear_pair_kernel<32><<<NUB64 + NIB64, 256>>>(hu, post_w_u, post_b_u, out_u, NU, NUB64,
                                                   hi, post_w_i, post_b_i, out_i, NI);
}

// round 15
// speedup vs baseline: 1.0010x; 1.0010x over previous
#include <cuda_runtime.h>
#include <cuda_bf16.h>
#include <cstdint>

#define NU 200000
#define NI 100000
#define NE 1000000
#define HD 64
#define OD 32
#define CHUNK 1024   // elements per scan chunk (256 threads * 4)

// ---------------- device scratch (static globals: allocation-guard safe) ----------------
__device__ float g_hu[(size_t)NU * HD];
__device__ float g_hi[(size_t)NI * HD];
__device__ float g_x1u[(size_t)NU * HD];
__device__ float g_x1i[(size_t)NI * HD];
__device__ int   g_csr_u2i[NE];
__device__ int   g_csr_i2u[NE];
__device__ int   g_rsu[NU + 1];
__device__ int   g_rsi[NI + 1];
__device__ int   g_curu[NU];
__device__ int   g_curi[NI];
__device__ int   g_partU[256];
__device__ int   g_partI[256];

// ---------------- zero both cursor arrays ----------------
__global__ void zero_both_kernel(int* __restrict__ curu, int* __restrict__ curi) {
    int i = blockIdx.x * blockDim.x + threadIdx.x;
    if (i < NU) curu[i] = 0;
    else if (i < NU + NI) curi[i - NU] = 0;
}

// ---------------- histogram both edge types ----------------
__global__ void hist_both_kernel(const int* __restrict__ ei_u2i, const int* __restrict__ ei_i2u,
                                 int* __restrict__ curi, int* __restrict__ curu, int eb) {
    int b = blockIdx.x;
    if (b < eb) {
        int e = b * 256 + threadIdx.x;
        if (e < NE) atomicAdd(&curi[__ldg(ei_u2i + NE + e)], 1);
    } else {
        int e = (b - eb) * 256 + threadIdx.x;
        if (e < NE) atomicAdd(&curu[__ldg(ei_i2u + NE + e)], 1);
    }
}

// ---------------- chunked scan phase 1: per-chunk sums (both types) ----------------
__global__ void chunk_both_kernel(const int* __restrict__ degI, int* __restrict__ partI, int nbi,
                                  const int* __restrict__ degU, int* __restrict__ partU) {
    __shared__ int sc[256];
    int tid = threadIdx.x;
    const int* deg; int* part; int n, b;
    if (blockIdx.x < nbi) { deg = degI; part = partI; n = NI; b = blockIdx.x; }
    else { deg = degU; part = partU; n = NU; b = blockIdx.x - nbi; }
    int base = b * CHUNK + tid * 4;
    int s = 0;
    #pragma unroll
    for (int j = 0; j < 4; j++) { int idx = base + j; if (idx < n) s += deg[idx]; }
    sc[tid] = s; __syncthreads();
    for (int d = 128; d; d >>= 1) { if (tid < d) sc[tid] += sc[tid + d]; __syncthreads(); }
    if (tid == 0) part[b] = sc[0];
}

// ---------------- chunked scan phase 2: scan partials for both (one block) ----------------
__device__ void scan_part_one(int* __restrict__ part, int nblk) {
    __shared__ int sc[256];
    int tid = threadIdx.x;
    int v = (tid < nblk) ? part[tid] : 0;
    sc[tid] = v; __syncthreads();
    for (int d = 1; d < 256; d <<= 1) {
        int t = (tid >= d) ? sc[tid - d] : 0;
        __syncthreads();
        sc[tid] += t;
        __syncthreads();
    }
    if (tid < nblk) part[tid] = sc[tid] - v;   // exclusive
    __syncthreads();
}

__global__ void scan_parts_kernel(int* __restrict__ partI, int nbi,
                                  int* __restrict__ partU, int nbu) {
    scan_part_one(partI, nbi);
    scan_part_one(partU, nbu);
}

// ---------------- chunked scan phase 3: write exclusive scan (both types) ----------------
__global__ void scanwrite_both_kernel(int* __restrict__ curi, const int* __restrict__ partI,
                                      int* __restrict__ rsi, int nbi,
                                      int* __restrict__ curu, const int* __restrict__ partU,
                                      int* __restrict__ rsu) {
    __shared__ int sc[256];
    int tid = threadIdx.x;
    int* deg; const int* part; int* rs; int n, b;
    if (blockIdx.x < nbi) { deg = curi; part = partI; rs = rsi; n = NI; b = blockIdx.x; }
    else { deg = curu; part = partU; rs = rsu; n = NU; b = blockIdx.x - nbi; }
    int base = b * CHUNK + tid * 4;
    int v[4]; int s = 0;
    #pragma unroll
    for (int j = 0; j < 4; j++) { int idx = base + j; v[j] = (idx < n) ? deg[idx] : 0; s += v[j]; }
    sc[tid] = s; __syncthreads();
    for (int d = 1; d < 256; d <<= 1) {
        int t = (tid >= d) ? sc[tid - d] : 0;
        __syncthreads();
        sc[tid] += t;
        __syncthreads();
    }
    int off = part[b] + (sc[tid] - s);
    #pragma unroll
    for (int j = 0; j < 4; j++) {
        int idx = base + j;
        if (idx < n) { rs[idx] = off; deg[idx] = off; }   // deg becomes fill cursor
        off += v[j];
    }
    if (b == 0 && tid == 0) rs[n] = NE;
}

// ---------------- fill both CSR arrays ----------------
__global__ void fill_both_kernel(const int* __restrict__ ei_u2i, const int* __restrict__ ei_i2u,
                                 int* __restrict__ curi, int* __restrict__ curu,
                                 int* __restrict__ csr_u2i, int* __restrict__ csr_i2u, int eb) {
    int b = blockIdx.x;
    if (b < eb) {
        int e = b * 256 + threadIdx.x;
        if (e < NE) {
            int pos = atomicAdd(&curi[__ldg(ei_u2i + NE + e)], 1);
            csr_u2i[pos] = __ldg(ei_u2i + e);
        }
    } else {
        int e = (b - eb) * 256 + threadIdx.x;
        if (e < NE) {
            int pos = atomicAdd(&curu[__ldg(ei_i2u + NE + e)], 1);
            csr_i2u[pos] = __ldg(ei_i2u + e);
        }
    }
}

// ---------------- fused linear pair: out[n,COLS] = x[n,64] @ W[COLS,64]^T + b ----------------
template <int COLS>
__global__ void __launch_bounds__(256) linear_pair_kernel(
    const float* __restrict__ x0, const float* __restrict__ W0,
    const float* __restrict__ b0, float* __restrict__ out0, int n0, int nb0,
    const float* __restrict__ x1, const float* __restrict__ W1,
    const float* __restrict__ b1, float* __restrict__ out1, int n1)
{
    const float *x, *W, *bias; float* out; int n, row0;
    if (blockIdx.x < nb0) { x = x0; W = W0; bias = b0; out = out0; n = n0; row0 = blockIdx.x * 64; }
    else { x = x1; W = W1; bias = b1; out = out1; n = n1; row0 = (blockIdx.x - nb0) * 64; }

    constexpr int WS = COLS + 4;
    __shared__ float sW[64 * WS];
    __shared__ float sX[64 * 68];
    int tid = threadIdx.x;

    for (int i = tid; i < COLS * 64; i += 256) {
        int c = i >> 6, k = i & 63;
        sW[k * WS + c] = W[i];
    }
    for (int i = tid; i < 64 * 16; i += 256) {
        int r = i >> 4, q = i & 15;
        int row = row0 + r;
        float4 v = make_float4(0.f, 0.f, 0.f, 0.f);
        if (row < n) v = __ldg((const float4*)(x + (size_t)row * 64) + q);
        *(float4*)&sX[r * 68 + q * 4] = v;
    }
    __syncthreads();

    constexpr int CPT = COLS / 4;
    int r = tid >> 2, sub = tid & 3;
    int c0 = sub * CPT;
    float o[CPT];
    #pragma unroll
    for (int i = 0; i < CPT; i++) o[i] = __ldg(bias + c0 + i);

    #pragma unroll 4
    for (int k = 0; k < 64; k++) {
        float xv = sX[r * 68 + k];
        #pragma unroll
        for (int i = 0; i < CPT / 4; i++) {
            float4 w = *(const float4*)&sW[k * WS + c0 + 4 * i];
            o[4 * i + 0] += xv * w.x;
            o[4 * i + 1] += xv * w.y;
            o[4 * i + 2] += xv * w.z;
            o[4 * i + 3] += xv * w.w;
        }
    }
    int row = row0 + r;
    if (row < n) {
        #pragma unroll
        for (int i = 0; i < CPT / 4; i++) {
            float4 v = make_float4(o[4 * i], o[4 * i + 1], o[4 * i + 2], o[4 * i + 3]);
            ((float4*)(out + (size_t)row * COLS + c0))[i] = v;
        }
    }
}

// ---- single-side fused conv pass (SEPARATE launch per side: preserves L2 residency) ----
// 256 threads, 64 rows/block. Gather: 4 threads/row, 2-edge unrolled, no shuffles.
// GEMM: 2 rows x 8 cols register tiles (2.67 FMA/LDS-byte). ~32 warps/SM.
__global__ void __launch_bounds__(256) combine_kernel(
    const float* __restrict__ feat, const float* __restrict__ h,
    const int* __restrict__ rs, const int* __restrict__ csr,
    const float* __restrict__ Wrel, const float* __restrict__ brel,
    const float* __restrict__ Wroot,
    float* __restrict__ out, int n)
{
    __shared__ float sW[64 * 68];   // 17408 B
    __shared__ float sA[64 * 68];   // 17408 B
    int tid = threadIdx.x;
    int row0 = blockIdx.x * 64;

    // load Wrel: W row-major [c][k] -> sW[k*68+c]  (issued before gather; no sync yet)
    for (int i = tid; i < 4096; i += 256) {
        int c = i >> 6, k = i & 63;
        sW[k * 68 + c] = __ldg(Wrel + i);
    }

    // ---- gather mean: 4 threads/row, each owns 16 floats; 2-edge unroll ----
    {
        int r = tid >> 2, q = tid & 3;      // row 0..63, quarter 0..3
        int row = row0 + r;
        bool valid = row < n;
        int e0 = valid ? __ldg(rs + row) : 0;
        int e1 = valid ? __ldg(rs + row + 1) : 0;
        float acc[16];
        #pragma unroll
        for (int i = 0; i < 16; i++) acc[i] = 0.f;

        int e = e0;
        for (; e + 2 <= e1; e += 2) {
            int s0 = __ldg(csr + e);
            int s1 = __ldg(csr + e + 1);
            const float4* p0 = (const float4*)(feat + (size_t)s0 * 64) + q * 4;
            const float4* p1 = (const float4*)(feat + (size_t)s1 * 64) + q * 4;
            float4 a0 = __ldg(p0),     a1 = __ldg(p0 + 1);
            float4 a2 = __ldg(p0 + 2), a3 = __ldg(p0 + 3);
            float4 b0 = __ldg(p1),     b1 = __ldg(p1 + 1);
            float4 b2 = __ldg(p1 + 2), b3 = __ldg(p1 + 3);
            acc[0]  += a0.x + b0.x;  acc[1]  += a0.y + b0.y;
            acc[2]  += a0.z + b0.z;  acc[3]  += a0.w + b0.w;
            acc[4]  += a1.x + b1.x;  acc[5]  += a1.y + b1.y;
            acc[6]  += a1.z + b1.z;  acc[7]  += a1.w + b1.w;
            acc[8]  += a2.x + b2.x;  acc[9]  += a2.y + b2.y;
            acc[10] += a2.z + b2.z;  acc[11] += a2.w + b2.w;
            acc[12] += a3.x + b3.x;  acc[13] += a3.y + b3.y;
            acc[14] += a3.z + b3.z;  acc[15] += a3.w + b3.w;
        }
        if (e < e1) {
            int s0 = __ldg(csr + e);
            const float4* p0 = (const float4*)(feat + (size_t)s0 * 64) + q * 4;
            float4 a0 = __ldg(p0),     a1 = __ldg(p0 + 1);
            float4 a2 = __ldg(p0 + 2), a3 = __ldg(p0 + 3);
            acc[0]  += a0.x;  acc[1]  += a0.y;  acc[2]  += a0.z;  acc[3]  += a0.w;
            acc[4]  += a1.x;  acc[5]  += a1.y;  acc[6]  += a1.z;  acc[7]  += a1.w;
            acc[8]  += a2.x;  acc[9]  += a2.y;  acc[10] += a2.z;  acc[11] += a2.w;
            acc[12] += a3.x;  acc[13] += a3.y;  acc[14] += a3.z;  acc[15] += a3.w;
        }
        float id = 1.f / fmaxf((float)(e1 - e0), 1.f);
        float* dst = &sA[r * 68 + q * 16];
        #pragma unroll
        for (int j = 0; j < 4; j++) {
            *(float4*)(dst + 4 * j) = make_float4(acc[4 * j] * id, acc[4 * j + 1] * id,
                                                  acc[4 * j + 2] * id, acc[4 * j + 3] * id);
        }
    }
    __syncthreads();

    // register tile: 2 rows x 8 cols
    int rg = tid >> 3, cg = tid & 7;
    int r0t = rg * 2, c0 = cg * 8;
    float o[16];
    {
        float4 b0 = __ldg((const float4*)(brel + c0));
        float4 b1 = __ldg((const float4*)(brel + c0) + 1);
        #pragma unroll
        for (int i = 0; i < 2; i++) {
            o[8 * i + 0] = b0.x;  o[8 * i + 1] = b0.y;
            o[8 * i + 2] = b0.z;  o[8 * i + 3] = b0.w;
            o[8 * i + 4] = b1.x;  o[8 * i + 5] = b1.y;
            o[8 * i + 6] = b1.z;  o[8 * i + 7] = b1.w;
        }
    }

    // GEMM1: o += mean @ Wrel^T
    #pragma unroll 4
    for (int k = 0; k < 64; k++) {
        float4 w0 = *(const float4*)&sW[k * 68 + c0];
        float4 w1 = *(const float4*)&sW[k * 68 + c0 + 4];
        #pragma unroll
        for (int i = 0; i < 2; i++) {
            float a = sA[(r0t + i) * 68 + k];
            o[8 * i + 0] += a * w0.x;  o[8 * i + 1] += a * w0.y;
            o[8 * i + 2] += a * w0.z;  o[8 * i + 3] += a * w0.w;
            o[8 * i + 4] += a * w1.x;  o[8 * i + 5] += a * w1.y;
            o[8 * i + 6] += a * w1.z;  o[8 * i + 7] += a * w1.w;
        }
    }
    __syncthreads();

    // reload: sW <- Wroot, sA <- h
    for (int i = tid; i < 4096; i += 256) {
        int c = i >> 6, k = i & 63;
        sW[k * 68 + c] = __ldg(Wroot + i);
    }
    for (int i = tid; i < 1024; i += 256) {
        int r = i >> 4, q = i & 15;
        int row = row0 + r;
        float4 v = make_float4(0.f, 0.f, 0.f, 0.f);
        if (row < n) v = __ldg((const float4*)(h + (size_t)row * 64) + q);
        *(float4*)&sA[r * 68 + q * 4] = v;
    }
    __syncthreads();

    // GEMM2: o += h @ Wroot^T
    #pragma unroll 4
    for (int k = 0; k < 64; k++) {
        float4 w0 = *(const float4*)&sW[k * 68 + c0];
        float4 w1 = *(const float4*)&sW[k * 68 + c0 + 4];
        #pragma unroll
        for (int i = 0; i < 2; i++) {
            float a = sA[(r0t + i) * 68 + k];
            o[8 * i + 0] += a * w0.x;  o[8 * i + 1] += a * w0.y;
            o[8 * i + 2] += a * w0.z;  o[8 * i + 3] += a * w0.w;
            o[8 * i + 4] += a * w1.x;  o[8 * i + 5] += a * w1.y;
            o[8 * i + 6] += a * w1.z;  o[8 * i + 7] += a * w1.w;
        }
    }

    // epilogue: + skip(h) -> relu -> store
    #pragma unroll
    for (int i = 0; i < 2; i++) {
        int row = row0 + r0t + i;
        if (row < n) {
            float4 s0 = *(const float4*)&sA[(r0t + i) * 68 + c0];
            float4 s1 = *(const float4*)&sA[(r0t + i) * 68 + c0 + 4];
            float4 v0, v1;
            v0.x = fmaxf(o[8 * i + 0] + s0.x, 0.f);
            v0.y = fmaxf(o[8 * i + 1] + s0.y, 0.f);
            v0.z = fmaxf(o[8 * i + 2] + s0.z, 0.f);
            v0.w = fmaxf(o[8 * i + 3] + s0.w, 0.f);
            v1.x = fmaxf(o[8 * i + 4] + s1.x, 0.f);
            v1.y = fmaxf(o[8 * i + 5] + s1.y, 0.f);
            v1.z = fmaxf(o[8 * i + 6] + s1.z, 0.f);
            v1.w = fmaxf(o[8 * i + 7] + s1.w, 0.f);
            float4* op = (float4*)(out + (size_t)row * 64 + c0);
            op[0] = v0;
            op[1] = v1;
        }
    }
}

// ---------------- host ----------------
extern "C" void kernel_launch(void* const* d_in, const int* in_sizes, int n_in,
                              void* d_out, int out_size)
{
    const float* x_user = (const float*)d_in[0];
    const float* x_item = (const float*)d_in[1];
    const int*   ei_u2i = (const int*)d_in[2];
    const int*   ei_i2u = (const int*)d_in[3];
    const float* pre_w_u = (const float*)d_in[4];
    const float* pre_b_u = (const float*)d_in[5];
    const float* pre_w_i = (const float*)d_in[6];
    const float* pre_b_i = (const float*)d_in[7];
    const float* c1u2i_wrel  = (const float*)d_in[8];
    const float* c1u2i_brel  = (const float*)d_in[9];
    const float* c1u2i_wroot = (const float*)d_in[10];
    const float* c1i2u_wrel  = (const float*)d_in[11];
    const float* c1i2u_brel  = (const float*)d_in[12];
    const float* c1i2u_wroot = (const float*)d_in[13];
    const float* c2u2i_wrel  = (const float*)d_in[14];
    const float* c2u2i_brel  = (const float*)d_in[15];
    const float* c2u2i_wroot = (const float*)d_in[16];
    const float* c2i2u_wrel  = (const float*)d_in[17];
    const float* c2i2u_brel  = (const float*)d_in[18];
    const float* c2i2u_wroot = (const float*)d_in[19];
    const float* post_w_u = (const float*)d_in[20];
    const float* post_b_u = (const float*)d_in[21];
    const float* post_w_i = (const float*)d_in[22];
    const float* post_b_i = (const float*)d_in[23];
    float* out_u = (float*)d_out;
    float* out_i = out_u + (size_t)NU * OD;

    float *hu, *hi, *x1u, *x1i;
    int *csr_u2i, *csr_i2u, *rsu, *rsi, *curu, *curi, *partU, *partI;
    cudaGetSymbolAddress((void**)&hu,  g_hu);
    cudaGetSymbolAddress((void**)&hi,  g_hi);
    cudaGetSymbolAddress((void**)&x1u, g_x1u);
    cudaGetSymbolAddress((void**)&x1i, g_x1i);
    cudaGetSymbolAddress((void**)&csr_u2i, g_csr_u2i);
    cudaGetSymbolAddress((void**)&csr_i2u, g_csr_i2u);
    cudaGetSymbolAddress((void**)&rsu,  g_rsu);
    cudaGetSymbolAddress((void**)&rsi,  g_rsi);
    cudaGetSymbolAddress((void**)&curu, g_curu);
    cudaGetSymbolAddress((void**)&curi, g_curi);
    cudaGetSymbolAddress((void**)&partU, g_partU);
    cudaGetSymbolAddress((void**)&partI, g_partI);

    const int EB = (NE + 255) / 256;
    const int NUB64 = (NU + 63) / 64, NIB64 = (NI + 63) / 64;
    const int NBLKI = (NI + CHUNK - 1) / CHUNK;   // 98
    const int NBLKU = (NU + CHUNK - 1) / CHUNK;   // 196

    // CSR build
    zero_both_kernel<<<(NU + NI + 255) / 256, 256>>>(curu, curi);
    hist_both_kernel<<<2 * EB, 256>>>(ei_u2i, ei_i2u, curi, curu, EB);
    chunk_both_kernel<<<NBLKI + NBLKU, 256>>>(curi, partI, NBLKI, curu, partU);
    scan_parts_kernel<<<1, 256>>>(partI, NBLKI, partU, NBLKU);
    scanwrite_both_kernel<<<NBLKI + NBLKU, 256>>>(curi, partI, rsi, NBLKI, curu, partU, rsu);
    fill_both_kernel<<<2 * EB, 256>>>(ei_u2i, ei_i2u, curi, curu, csr_u2i, csr_i2u, EB);

    // preprocess linears
    linear_pair_kernel<64><<<NUB64 + NIB64, 256>>>(x_user, pre_w_u, pre_b_u, hu, NU, NUB64,
                                                   x_item, pre_w_i, pre_b_i, hi, NI);
    // layer 1 (separate launches: each pass keeps its feature table L2-resident)
    combine_kernel<<<NIB64, 256>>>(hu, hi, rsi, csr_u2i,
                                   c1u2i_wrel, c1u2i_brel, c1u2i_wroot, x1i, NI);
    combine_kernel<<<NUB64, 256>>>(hi, hu, rsu, csr_i2u,
                                   c1i2u_wrel, c1i2u_brel, c1i2u_wroot, x1u, NU);
    // layer 2 (outputs overwrite pre-linear buffers)
    combine_kernel<<<NIB64, 256>>>(x1u, x1i, rsi, csr_u2i,
                                   c2u2i_wrel, c2u2i_brel, c2u2i_wroot, hi, NI);
    combine_kernel<<<NUB64, 256>>>(x1i, x1u, rsu, csr_i2u,
                                   c2i2u_wrel, c2i2u_brel, c2i2u_wroot, hu, NU);
    // postprocess linears -> output
    linear_pair_kernel<32><<<NUB64 + NIB64, 256>>>(hu, post_w_u, post_b_u, out_u, NU, NUB64,
                                                   hi, post_w_i, post_b_i, out_i, NI);
}

// round 17
// speedup vs baseline: 1.3323x; 1.3309x over previous
#include <cuda_runtime.h>
#include <cuda_bf16.h>
#include <cstdint>

#define NU 200000
#define NI 100000
#define NE 1000000
#define HD 64
#define OD 32
#define CHUNK 1024   // elements per scan chunk (256 threads * 4)

// ---------------- device scratch (static globals: allocation-guard safe) ----------------
__device__ float g_hu[(size_t)NU * HD];
__device__ float g_hi[(size_t)NI * HD];
__device__ float g_x1u[(size_t)NU * HD];
__device__ float g_x1i[(size_t)NI * HD];
__device__ int   g_csr_u2i[NE];
__device__ int   g_csr_i2u[NE];
__device__ int   g_rsu[NU + 1];
__device__ int   g_rsi[NI + 1];
__device__ int   g_curu[NU];
__device__ int   g_curi[NI];
__device__ int   g_partU[256];
__device__ int   g_partI[256];

// ---------------- zero both cursor arrays ----------------
__global__ void zero_both_kernel(int* __restrict__ curu, int* __restrict__ curi) {
    int i = blockIdx.x * blockDim.x + threadIdx.x;
    if (i < NU) curu[i] = 0;
    else if (i < NU + NI) curi[i - NU] = 0;
}

// ---------------- histogram both edge types ----------------
__global__ void hist_both_kernel(const int* __restrict__ ei_u2i, const int* __restrict__ ei_i2u,
                                 int* __restrict__ curi, int* __restrict__ curu, int eb) {
    int b = blockIdx.x;
    if (b < eb) {
        int e = b * 256 + threadIdx.x;
        if (e < NE) atomicAdd(&curi[__ldg(ei_u2i + NE + e)], 1);
    } else {
        int e = (b - eb) * 256 + threadIdx.x;
        if (e < NE) atomicAdd(&curu[__ldg(ei_i2u + NE + e)], 1);
    }
}

// ---------------- chunked scan phase 1: per-chunk sums (both types) ----------------
__global__ void chunk_both_kernel(const int* __restrict__ degI, int* __restrict__ partI, int nbi,
                                  const int* __restrict__ degU, int* __restrict__ partU) {
    __shared__ int sc[256];
    int tid = threadIdx.x;
    const int* deg; int* part; int n, b;
    if (blockIdx.x < nbi) { deg = degI; part = partI; n = NI; b = blockIdx.x; }
    else { deg = degU; part = partU; n = NU; b = blockIdx.x - nbi; }
    int base = b * CHUNK + tid * 4;
    int s = 0;
    #pragma unroll
    for (int j = 0; j < 4; j++) { int idx = base + j; if (idx < n) s += deg[idx]; }
    sc[tid] = s; __syncthreads();
    for (int d = 128; d; d >>= 1) { if (tid < d) sc[tid] += sc[tid + d]; __syncthreads(); }
    if (tid == 0) part[b] = sc[0];
}

// ---------------- chunked scan phase 2: scan partials for both (one block) ----------------
__device__ void scan_part_one(int* __restrict__ part, int nblk) {
    __shared__ int sc[256];
    int tid = threadIdx.x;
    int v = (tid < nblk) ? part[tid] : 0;
    sc[tid] = v; __syncthreads();
    for (int d = 1; d < 256; d <<= 1) {
        int t = (tid >= d) ? sc[tid - d] : 0;
        __syncthreads();
        sc[tid] += t;
        __syncthreads();
    }
    if (tid < nblk) part[tid] = sc[tid] - v;   // exclusive
    __syncthreads();
}

__global__ void scan_parts_kernel(int* __restrict__ partI, int nbi,
                                  int* __restrict__ partU, int nbu) {
    scan_part_one(partI, nbi);
    scan_part_one(partU, nbu);
}

// ---------------- chunked scan phase 3: write exclusive scan (both types) ----------------
__global__ void scanwrite_both_kernel(int* __restrict__ curi, const int* __restrict__ partI,
                                      int* __restrict__ rsi, int nbi,
                                      int* __restrict__ curu, const int* __restrict__ partU,
                                      int* __restrict__ rsu) {
    __shared__ int sc[256];
    int tid = threadIdx.x;
    int* deg; const int* part; int* rs; int n, b;
    if (blockIdx.x < nbi) { deg = curi; part = partI; rs = rsi; n = NI; b = blockIdx.x; }
    else { deg = curu; part = partU; rs = rsu; n = NU; b = blockIdx.x - nbi; }
    int base = b * CHUNK + tid * 4;
    int v[4]; int s = 0;
    #pragma unroll
    for (int j = 0; j < 4; j++) { int idx = base + j; v[j] = (idx < n) ? deg[idx] : 0; s += v[j]; }
    sc[tid] = s; __syncthreads();
    for (int d = 1; d < 256; d <<= 1) {
        int t = (tid >= d) ? sc[tid - d] : 0;
        __syncthreads();
        sc[tid] += t;
        __syncthreads();
    }
    int off = part[b] + (sc[tid] - s);
    #pragma unroll
    for (int j = 0; j < 4; j++) {
        int idx = base + j;
        if (idx < n) { rs[idx] = off; deg[idx] = off; }   // deg becomes fill cursor
        off += v[j];
    }
    if (b == 0 && tid == 0) rs[n] = NE;
}

// ---------------- fill both CSR arrays ----------------
__global__ void fill_both_kernel(const int* __restrict__ ei_u2i, const int* __restrict__ ei_i2u,
                                 int* __restrict__ curi, int* __restrict__ curu,
                                 int* __restrict__ csr_u2i, int* __restrict__ csr_i2u, int eb) {
    int b = blockIdx.x;
    if (b < eb) {
        int e = b * 256 + threadIdx.x;
        if (e < NE) {
            int pos = atomicAdd(&curi[__ldg(ei_u2i + NE + e)], 1);
            csr_u2i[pos] = __ldg(ei_u2i + e);
        }
    } else {
        int e = (b - eb) * 256 + threadIdx.x;
        if (e < NE) {
            int pos = atomicAdd(&curu[__ldg(ei_i2u + NE + e)], 1);
            csr_i2u[pos] = __ldg(ei_i2u + e);
        }
    }
}

// ---------------- fused linear pair: out[n,COLS] = x[n,64] @ W[COLS,64]^T + b ----------------
template <int COLS>
__global__ void __launch_bounds__(256) linear_pair_kernel(
    const float* __restrict__ x0, const float* __restrict__ W0,
    const float* __restrict__ b0, float* __restrict__ out0, int n0, int nb0,
    const float* __restrict__ x1, const float* __restrict__ W1,
    const float* __restrict__ b1, float* __restrict__ out1, int n1)
{
    const float *x, *W, *bias; float* out; int n, row0;
    if (blockIdx.x < nb0) { x = x0; W = W0; bias = b0; out = out0; n = n0; row0 = blockIdx.x * 64; }
    else { x = x1; W = W1; bias = b1; out = out1; n = n1; row0 = (blockIdx.x - nb0) * 64; }

    constexpr int WS = COLS + 4;
    __shared__ float sW[64 * WS];
    __shared__ float sX[64 * 68];
    int tid = threadIdx.x;

    for (int i = tid; i < COLS * 64; i += 256) {
        int c = i >> 6, k = i & 63;
        sW[k * WS + c] = W[i];
    }
    for (int i = tid; i < 64 * 16; i += 256) {
        int r = i >> 4, q = i & 15;
        int row = row0 + r;
        float4 v = make_float4(0.f, 0.f, 0.f, 0.f);
        if (row < n) v = __ldg((const float4*)(x + (size_t)row * 64) + q);
        *(float4*)&sX[r * 68 + q * 4] = v;
    }
    __syncthreads();

    constexpr int CPT = COLS / 4;
    int r = tid >> 2, sub = tid & 3;
    int c0 = sub * CPT;
    float o[CPT];
    #pragma unroll
    for (int i = 0; i < CPT; i++) o[i] = __ldg(bias + c0 + i);

    #pragma unroll 4
    for (int k = 0; k < 64; k++) {
        float xv = sX[r * 68 + k];
        #pragma unroll
        for (int i = 0; i < CPT / 4; i++) {
            float4 w = *(const float4*)&sW[k * WS + c0 + 4 * i];
            o[4 * i + 0] += xv * w.x;
            o[4 * i + 1] += xv * w.y;
            o[4 * i + 2] += xv * w.z;
            o[4 * i + 3] += xv * w.w;
        }
    }
    int row = row0 + r;
    if (row < n) {
        #pragma unroll
        for (int i = 0; i < CPT / 4; i++) {
            float4 v = make_float4(o[4 * i], o[4 * i + 1], o[4 * i + 2], o[4 * i + 3]);
            ((float4*)(out + (size_t)row * COLS + c0))[i] = v;
        }
    }
}

// ---- dual-side fused conv layer (round-10 GEMM body + coalesced gather) ----
// 128 threads, 64 rows/block. Gather: lane q owns the q-th 16B chunk of a row;
// 16 lanes cover one row's 256B contiguously (4 fully-used lines per warp instr).
// GEMM: 4 rows x 8 cols register tiles (o[32], 2.67 FMA/LDS-float, FFMA-bound).
__global__ void __launch_bounds__(128) combine_dual_kernel(
    const float* __restrict__ featA, const float* __restrict__ hA,
    const int* __restrict__ rsA, const int* __restrict__ csrA,
    const float* __restrict__ WrelA, const float* __restrict__ brelA,
    const float* __restrict__ WrootA, float* __restrict__ outA, int nA, int nbA,
    const float* __restrict__ featB, const float* __restrict__ hB,
    const int* __restrict__ rsB, const int* __restrict__ csrB,
    const float* __restrict__ WrelB, const float* __restrict__ brelB,
    const float* __restrict__ WrootB, float* __restrict__ outB, int nB)
{
    __shared__ float sW[64 * 68];   // 17408 B
    __shared__ float sA[64 * 68];   // 17408 B

    const float *feat, *h, *Wrel, *brel, *Wroot; const int *rs, *csr;
    float* out; int n, row0;
    if (blockIdx.x < nbA) {
        feat = featA; h = hA; rs = rsA; csr = csrA;
        Wrel = WrelA; brel = brelA; Wroot = WrootA; out = outA; n = nA;
        row0 = blockIdx.x * 64;
    } else {
        feat = featB; h = hB; rs = rsB; csr = csrB;
        Wrel = WrelB; brel = brelB; Wroot = WrootB; out = outB; n = nB;
        row0 = (blockIdx.x - nbA) * 64;
    }

    int tid = threadIdx.x;

    // load Wrel: W row-major [c][k] -> sW[k*68+c]  (issued before gather; no sync yet)
    for (int i = tid; i < 4096; i += 128) {
        int c = i >> 6, k = i & 63;
        sW[k * 68 + c] = __ldg(Wrel + i);
    }

    // ---- gather mean (coalesced): lane q = 16B chunk, 8 rows in flight, 8 passes ----
    {
        int q = tid & 15;                // chunk 0..15 (16B each)
        int rg = tid >> 4;               // row-group lane 0..7
        #pragma unroll 1
        for (int it = 0; it < 8; it++) {
            int r = it * 8 + rg;
            int row = row0 + r;
            bool valid = row < n;
            int e0 = valid ? __ldg(rs + row) : 0;
            int e1 = valid ? __ldg(rs + row + 1) : 0;
            float4 acc = make_float4(0.f, 0.f, 0.f, 0.f);
            int e = e0;
            for (; e + 2 <= e1; e += 2) {
                int s0 = __ldg(csr + e);
                int s1 = __ldg(csr + e + 1);
                float4 v0 = __ldg((const float4*)(feat + (size_t)s0 * 64) + q);
                float4 v1 = __ldg((const float4*)(feat + (size_t)s1 * 64) + q);
                acc.x += v0.x + v1.x;  acc.y += v0.y + v1.y;
                acc.z += v0.z + v1.z;  acc.w += v0.w + v1.w;
            }
            if (e < e1) {
                int s0 = __ldg(csr + e);
                float4 v0 = __ldg((const float4*)(feat + (size_t)s0 * 64) + q);
                acc.x += v0.x;  acc.y += v0.y;  acc.z += v0.z;  acc.w += v0.w;
            }
            float id = 1.f / fmaxf((float)(e1 - e0), 1.f);
            *(float4*)&sA[r * 68 + q * 4] =
                make_float4(acc.x * id, acc.y * id, acc.z * id, acc.w * id);
        }
    }
    __syncthreads();

    // register tile: rows ro..ro+3, cols c0..c0+7
    int rg = tid >> 3, cg = tid & 7;
    int ro = rg * 4, c0 = cg * 8;
    float o[32];
    {
        float4 b0 = __ldg((const float4*)(brel + c0));
        float4 b1 = __ldg((const float4*)(brel + c0) + 1);
        #pragma unroll
        for (int i = 0; i < 4; i++) {
            o[8 * i + 0] = b0.x;  o[8 * i + 1] = b0.y;
            o[8 * i + 2] = b0.z;  o[8 * i + 3] = b0.w;
            o[8 * i + 4] = b1.x;  o[8 * i + 5] = b1.y;
            o[8 * i + 6] = b1.z;  o[8 * i + 7] = b1.w;
        }
    }

    // GEMM1: o += mean @ Wrel^T
    #pragma unroll 4
    for (int k = 0; k < 64; k++) {
        float4 w0 = *(const float4*)&sW[k * 68 + c0];
        float4 w1 = *(const float4*)&sW[k * 68 + c0 + 4];
        #pragma unroll
        for (int i = 0; i < 4; i++) {
            float a = sA[(ro + i) * 68 + k];
            o[8 * i + 0] += a * w0.x;  o[8 * i + 1] += a * w0.y;
            o[8 * i + 2] += a * w0.z;  o[8 * i + 3] += a * w0.w;
            o[8 * i + 4] += a * w1.x;  o[8 * i + 5] += a * w1.y;
            o[8 * i + 6] += a * w1.z;  o[8 * i + 7] += a * w1.w;
        }
    }
    __syncthreads();

    // reload: sW <- Wroot, sA <- h
    for (int i = tid; i < 4096; i += 128) {
        int c = i >> 6, k = i & 63;
        sW[k * 68 + c] = __ldg(Wroot + i);
    }
    for (int i = tid; i < 1024; i += 128) {
        int r = i >> 4, q = i & 15;
        int row = row0 + r;
        float4 v = make_float4(0.f, 0.f, 0.f, 0.f);
        if (row < n) v = __ldg((const float4*)(h + (size_t)row * 64) + q);
        *(float4*)&sA[r * 68 + q * 4] = v;
    }
    __syncthreads();

    // GEMM2: o += h @ Wroot^T
    #pragma unroll 4
    for (int k = 0; k < 64; k++) {
        float4 w0 = *(const float4*)&sW[k * 68 + c0];
        float4 w1 = *(const float4*)&sW[k * 68 + c0 + 4];
        #pragma unroll
        for (int i = 0; i < 4; i++) {
            float a = sA[(ro + i) * 68 + k];
            o[8 * i + 0] += a * w0.x;  o[8 * i + 1] += a * w0.y;
            o[8 * i + 2] += a * w0.z;  o[8 * i + 3] += a * w0.w;
            o[8 * i + 4] += a * w1.x;  o[8 * i + 5] += a * w1.y;
            o[8 * i + 6] += a * w1.z;  o[8 * i + 7] += a * w1.w;
        }
    }

    // epilogue: + skip(h) -> relu -> store
    #pragma unroll
    for (int i = 0; i < 4; i++) {
        int row = row0 + ro + i;
        if (row < n) {
            float4 s0 = *(const float4*)&sA[(ro + i) * 68 + c0];
            float4 s1 = *(const float4*)&sA[(ro + i) * 68 + c0 + 4];
            float4 v0, v1;
            v0.x = fmaxf(o[8 * i + 0] + s0.x, 0.f);
            v0.y = fmaxf(o[8 * i + 1] + s0.y, 0.f);
            v0.z = fmaxf(o[8 * i + 2] + s0.z, 0.f);
            v0.w = fmaxf(o[8 * i + 3] + s0.w, 0.f);
            v1.x = fmaxf(o[8 * i + 4] + s1.x, 0.f);
            v1.y = fmaxf(o[8 * i + 5] + s1.y, 0.f);
            v1.z = fmaxf(o[8 * i + 6] + s1.z, 0.f);
            v1.w = fmaxf(o[8 * i + 7] + s1.w, 0.f);
            float4* op = (float4*)(out + (size_t)row * 64 + c0);
            op[0] = v0;
            op[1] = v1;
        }
    }
}

// ---------------- host ----------------
extern "C" void kernel_launch(void* const* d_in, const int* in_sizes, int n_in,
                              void* d_out, int out_size)
{
    const float* x_user = (const float*)d_in[0];
    const float* x_item = (const float*)d_in[1];
    const int*   ei_u2i = (const int*)d_in[2];
    const int*   ei_i2u = (const int*)d_in[3];
    const float* pre_w_u = (const float*)d_in[4];
    const float* pre_b_u = (const float*)d_in[5];
    const float* pre_w_i = (const float*)d_in[6];
    const float* pre_b_i = (const float*)d_in[7];
    const float* c1u2i_wrel  = (const float*)d_in[8];
    const float* c1u2i_brel  = (const float*)d_in[9];
    const float* c1u2i_wroot = (const float*)d_in[10];
    const float* c1i2u_wrel  = (const float*)d_in[11];
    const float* c1i2u_brel  = (const float*)d_in[12];
    const float* c1i2u_wroot = (const float*)d_in[13];
    const float* c2u2i_wrel  = (const float*)d_in[14];
    const float* c2u2i_brel  = (const float*)d_in[15];
    const float* c2u2i_wroot = (const float*)d_in[16];
    const float* c2i2u_wrel  = (const float*)d_in[17];
    const float* c2i2u_brel  = (const float*)d_in[18];
    const float* c2i2u_wroot = (const float*)d_in[19];
    const float* post_w_u = (const float*)d_in[20];
    const float* post_b_u = (const float*)d_in[21];
    const float* post_w_i = (const float*)d_in[22];
    const float* post_b_i = (const float*)d_in[23];
    float* out_u = (float*)d_out;
    float* out_i = out_u + (size_t)NU * OD;

    float *hu, *hi, *x1u, *x1i;
    int *csr_u2i, *csr_i2u, *rsu, *rsi, *curu, *curi, *partU, *partI;
    cudaGetSymbolAddress((void**)&hu,  g_hu);
    cudaGetSymbolAddress((void**)&hi,  g_hi);
    cudaGetSymbolAddress((void**)&x1u, g_x1u);
    cudaGetSymbolAddress((void**)&x1i, g_x1i);
    cudaGetSymbolAddress((void**)&csr_u2i, g_csr_u2i);
    cudaGetSymbolAddress((void**)&csr_i2u, g_csr_i2u);
    cudaGetSymbolAddress((void**)&rsu,  g_rsu);
    cudaGetSymbolAddress((void**)&rsi,  g_rsi);
    cudaGetSymbolAddress((void**)&curu, g_curu);
    cudaGetSymbolAddress((void**)&curi, g_curi);
    cudaGetSymbolAddress((void**)&partU, g_partU);
    cudaGetSymbolAddress((void**)&partI, g_partI);

    const int EB = (NE + 255) / 256;
    const int NUB64 = (NU + 63) / 64, NIB64 = (NI + 63) / 64;
    const int NBLKI = (NI + CHUNK - 1) / CHUNK;   // 98
    const int NBLKU = (NU + CHUNK - 1) / CHUNK;   // 196

    // CSR build
    zero_both_kernel<<<(NU + NI + 255) / 256, 256>>>(curu, curi);
    hist_both_kernel<<<2 * EB, 256>>>(ei_u2i, ei_i2u, curi, curu, EB);
    chunk_both_kernel<<<NBLKI + NBLKU, 256>>>(curi, partI, NBLKI, curu, partU);
    scan_parts_kernel<<<1, 256>>>(partI, NBLKI, partU, NBLKU);
    scanwrite_both_kernel<<<NBLKI + NBLKU, 256>>>(curi, partI, rsi, NBLKI, curu, partU, rsu);
    fill_both_kernel<<<2 * EB, 256>>>(ei_u2i, ei_i2u, curi, curu, csr_u2i, csr_i2u, EB);

    // preprocess linears
    linear_pair_kernel<64><<<NUB64 + NIB64, 256>>>(x_user, pre_w_u, pre_b_u, hu, NU, NUB64,
                                                   x_item, pre_w_i, pre_b_i, hi, NI);
    // layer 1: items-dst + users-dst in one launch
    combine_dual_kernel<<<NIB64 + NUB64, 128>>>(
        hu, hi, rsi, csr_u2i, c1u2i_wrel, c1u2i_brel, c1u2i_wroot, x1i, NI, NIB64,
        hi, hu, rsu, csr_i2u, c1i2u_wrel, c1i2u_brel, c1i2u_wroot, x1u, NU);
    // layer 2 (outputs overwrite pre-linear buffers)
    combine_dual_kernel<<<NIB64 + NUB64, 128>>>(
        x1u, x1i, rsi, csr_u2i, c2u2i_wrel, c2u2i_brel, c2u2i_wroot, hi, NI, NIB64,
        x1i, x1u, rsu, csr_i2u, c2i2u_wrel, c2i2u_brel, c2i2u_wroot, hu, NU);
    // postprocess linears -> output
    linear_pair_kernel<32><<<NUB64 + NIB64, 256>>>(hu, post_w_u, post_b_u, out_u, NU, NUB64,
                                                   hi, post_w_i, post_b_i, out_i, NI);
}